// round 3
// baseline (speedup 1.0000x reference)
#include <cuda_runtime.h>

typedef unsigned long long u64;

__device__ __forceinline__ u64 sub2(u64 a, u64 b) {
    u64 d; asm("sub.rn.f32x2 %0, %1, %2;" : "=l"(d) : "l"(a), "l"(b)); return d;
}
__device__ __forceinline__ void unpk(u64 v, float& lo, float& hi) {
    asm("mov.b64 {%0, %1}, %2;" : "=f"(lo), "=f"(hi) : "l"(v));
}

constexpr int B = 1024, F = 784, D = 512;
constexpr int TB = 64, TD = 64, TF = 56;   // 784 = 14 * 56
constexpr int SX = 60;                      // padded smem stride; SX/4=15 (odd mod 8) -> conflict-free LDS.128
constexpr int NSTEP = F / TF;               // 14
constexpr int FSPLIT = 2;                   // k-steps split across 2 CTAs in z
constexpr int KH = NSTEP / FSPLIT;          // 7

// Partial results: [fsplit][B*D] = 4 MB device scratch (allocation-free rule).
__device__ float g_part[FSPLIT][B * D];

__global__ __launch_bounds__(256, 2)
void dendral_main(const float* __restrict__ x,
                  const float* __restrict__ wmin,
                  const float* __restrict__ wmax)
{
    __shared__ float sx [TB * SX];
    __shared__ float smn[TD * SX];
    __shared__ float smx[TD * SX];

    const int tid = threadIdx.x;
    const int tx  = tid & 15;    // d lane
    const int ty  = tid >> 4;    // b lane
    const int d0  = blockIdx.x * TD;
    const int b0  = blockIdx.y * TB;
    const int zh  = blockIdx.z;             // F-half
    const int k0  = zh * KH;

    const float INF = __int_as_float(0x7F800000);
    float2 acc[4][4];
    #pragma unroll
    for (int i = 0; i < 4; ++i)
        #pragma unroll
        for (int j = 0; j < 4; ++j) acc[i][j] = make_float2(INF, INF);

    for (int k = k0; k < k0 + KH; ++k) {
        const int f0 = k * TF;
        __syncthreads();

        // Stage tiles: 64 rows x 14 float4 per array.
        #pragma unroll
        for (int t = 0; t < 4; ++t) {
            int idx = tid + t * 256;
            if (idx < 896) {
                int row = idx / 14;
                int c4  = idx % 14;
                float4 vx = *(const float4*)&x   [(b0 + row) * F + f0 + c4 * 4];
                float4 vn = *(const float4*)&wmin[(d0 + row) * F + f0 + c4 * 4];
                float4 vm = *(const float4*)&wmax[(d0 + row) * F + f0 + c4 * 4];
                *(float4*)&sx [row * SX + c4 * 4] = vx;
                *(float4*)&smn[row * SX + c4 * 4] = vn;
                *(float4*)&smx[row * SX + c4 * 4] = vm;
            }
        }
        __syncthreads();

        #pragma unroll 2
        for (int f = 0; f < TF; f += 4) {
            ulonglong2 xv[4];
            #pragma unroll
            for (int j = 0; j < 4; ++j)
                xv[j] = *(const ulonglong2*)&sx[(ty + 16 * j) * SX + f];

            // Load W-frag per i inside the loop: fewer live registers,
            // keeps us under the 128-reg cap for 2 CTAs/SM.
            #pragma unroll
            for (int i = 0; i < 4; ++i) {
                ulonglong2 nv = *(const ulonglong2*)&smn[(tx + 16 * i) * SX + f];
                ulonglong2 mv = *(const ulonglong2*)&smx[(tx + 16 * i) * SX + f];
                #pragma unroll
                for (int j = 0; j < 4; ++j) {
                    u64 t1a = sub2(xv[j].x, nv.x);   // x - Wmin  (f 0/1)
                    u64 t2a = sub2(mv.x, xv[j].x);   // Wmax - x
                    u64 t1b = sub2(xv[j].y, nv.y);   // f 2/3
                    u64 t2b = sub2(mv.y, xv[j].y);

                    float a0, a1, c0, c1, e0, e1, g0, g1;
                    unpk(t1a, a0, a1);
                    unpk(t2a, c0, c1);
                    unpk(t1b, e0, e1);
                    unpk(t2b, g0, g1);

                    float m0 = fminf(a0, c0);
                    float m1 = fminf(a1, c1);
                    float m2 = fminf(e0, g0);
                    float m3 = fminf(e1, g1);
                    acc[i][j].x = fminf(acc[i][j].x, m0);
                    acc[i][j].y = fminf(acc[i][j].y, m1);
                    acc[i][j].x = fminf(acc[i][j].x, m2);
                    acc[i][j].y = fminf(acc[i][j].y, m3);
                }
            }
        }
    }

    float* part = g_part[zh];
    #pragma unroll
    for (int i = 0; i < 4; ++i)
        #pragma unroll
        for (int j = 0; j < 4; ++j) {
            int b = b0 + ty + 16 * j;
            int d = d0 + tx + 16 * i;
            part[b * D + d] = fminf(acc[i][j].x, acc[i][j].y);
        }
}

__global__ __launch_bounds__(256, 8)
void dendral_combine(float* __restrict__ out)
{
    int idx = (blockIdx.x * 256 + threadIdx.x) * 4;
    float4 p0 = *(const float4*)&g_part[0][idx];
    float4 p1 = *(const float4*)&g_part[1][idx];
    float4 r;
    r.x = fminf(p0.x, p1.x);
    r.y = fminf(p0.y, p1.y);
    r.z = fminf(p0.z, p1.z);
    r.w = fminf(p0.w, p1.w);
    *(float4*)&out[idx] = r;
}

extern "C" void kernel_launch(void* const* d_in, const int* in_sizes, int n_in,
                              void* d_out, int out_size)
{
    const float* x    = (const float*)d_in[0];
    const float* wmin = (const float*)d_in[1];
    const float* wmax = (const float*)d_in[2];
    float* out = (float*)d_out;

    dim3 grid(D / TD, B / TB, FSPLIT);     // (8, 16, 2) = 256 CTAs
    dendral_main<<<grid, 256>>>(x, wmin, wmax);

    int n4 = (B * D) / 4;                  // 131072 quads
    dendral_combine<<<n4 / 256, 256>>>(out);
}

// round 5
// speedup vs baseline: 1.4399x; 1.4399x over previous
#include <cuda_runtime.h>
#include <cuda_fp16.h>

constexpr int B = 1024, F = 784, D = 512;
constexpr int TB = 64, TD = 64, TF = 112;    // 784 = 7 * 112
constexpr int SXH = 120;                      // smem stride in halfs: 240B = 15 x 16B (odd) -> conflict-friendly
constexpr int NSTEP = F / TF;                 // 7

union U4H {
    uint4 u;
    __half2 h[4];
};

__device__ __forceinline__ unsigned h2u(__half2 v) {
    union { __half2 h; unsigned u; } c; c.h = v; return c.u;
}

__global__ __launch_bounds__(256)
void dendral_kernel(const float* __restrict__ x,
                    const float* __restrict__ wmin,
                    const float* __restrict__ wmax,
                    float* __restrict__ out)
{
    __shared__ __half sx [TB * SXH];
    __shared__ __half smn[TD * SXH];
    __shared__ __half smx[TD * SXH];

    const int tid = threadIdx.x;
    const int tx  = tid & 15;    // d lane
    const int ty  = tid >> 4;    // b lane
    const int d0  = blockIdx.x * TD;
    const int b0  = blockIdx.y * TB;

    // +inf in both half lanes
    const __half2 INF2 = __halves2half2(__ushort_as_half(0x7C00), __ushort_as_half(0x7C00));
    __half2 acc[4][4];
    #pragma unroll
    for (int i = 0; i < 4; ++i)
        #pragma unroll
        for (int j = 0; j < 4; ++j) acc[i][j] = INF2;

    for (int k = 0; k < NSTEP; ++k) {
        const int f0 = k * TF;
        __syncthreads();   // protect smem reuse from previous step

        // Stage + convert: 64 rows x 28 float4 = 1792 float4 per array; 7 per thread.
        #pragma unroll
        for (int t = 0; t < 7; ++t) {
            int idx = tid + t * 256;
            int row = idx / 28;
            int c4  = idx % 28;

            float4 vx = *(const float4*)&x   [(b0 + row) * F + f0 + c4 * 4];
            float4 vn = *(const float4*)&wmin[(d0 + row) * F + f0 + c4 * 4];
            float4 vm = *(const float4*)&wmax[(d0 + row) * F + f0 + c4 * 4];

            __half2 hx01 = __floats2half2_rn(vx.x, vx.y);
            __half2 hx23 = __floats2half2_rn(vx.z, vx.w);
            __half2 hn01 = __floats2half2_rn(vn.x, vn.y);
            __half2 hn23 = __floats2half2_rn(vn.z, vn.w);
            __half2 hm01 = __floats2half2_rn(vm.x, vm.y);
            __half2 hm23 = __floats2half2_rn(vm.z, vm.w);

            int so = row * SXH + c4 * 4;          // 8-byte aligned
            *(uint2*)&sx [so] = make_uint2(h2u(hx01), h2u(hx23));
            *(uint2*)&smn[so] = make_uint2(h2u(hn01), h2u(hn23));
            *(uint2*)&smx[so] = make_uint2(h2u(hm01), h2u(hm23));
        }
        __syncthreads();

        #pragma unroll 2
        for (int f = 0; f < TF; f += 8) {
            U4H xv[4];
            #pragma unroll
            for (int j = 0; j < 4; ++j)
                xv[j].u = *(const uint4*)&sx[(ty + 16 * j) * SXH + f];

            #pragma unroll
            for (int i = 0; i < 4; ++i) {
                U4H nv, mv;
                nv.u = *(const uint4*)&smn[(tx + 16 * i) * SXH + f];
                mv.u = *(const uint4*)&smx[(tx + 16 * i) * SXH + f];
                #pragma unroll
                for (int j = 0; j < 4; ++j) {
                    __half2 c0 = __hmin2(__hsub2(xv[j].h[0], nv.h[0]), __hsub2(mv.h[0], xv[j].h[0]));
                    __half2 c1 = __hmin2(__hsub2(xv[j].h[1], nv.h[1]), __hsub2(mv.h[1], xv[j].h[1]));
                    __half2 c2 = __hmin2(__hsub2(xv[j].h[2], nv.h[2]), __hsub2(mv.h[2], xv[j].h[2]));
                    __half2 c3 = __hmin2(__hsub2(xv[j].h[3], nv.h[3]), __hsub2(mv.h[3], xv[j].h[3]));
                    __half2 d01 = __hmin2(c0, c1);
                    __half2 d23 = __hmin2(c2, c3);
                    acc[i][j] = __hmin2(acc[i][j], __hmin2(d01, d23));
                }
            }
        }
    }

    // Epilogue: min the two half lanes, store fp32, coalesced in d.
    #pragma unroll
    for (int i = 0; i < 4; ++i)
        #pragma unroll
        for (int j = 0; j < 4; ++j) {
            float lo = __low2float (acc[i][j]);
            float hi = __high2float(acc[i][j]);
            int b = b0 + ty + 16 * j;
            int d = d0 + tx + 16 * i;
            out[b * D + d] = fminf(lo, hi);
        }
}

extern "C" void kernel_launch(void* const* d_in, const int* in_sizes, int n_in,
                              void* d_out, int out_size)
{
    const float* x    = (const float*)d_in[0];
    const float* wmin = (const float*)d_in[1];
    const float* wmax = (const float*)d_in[2];
    float* out = (float*)d_out;

    dim3 grid(D / TD, B / TB);   // (8, 16) = 128 CTAs
    dendral_kernel<<<grid, 256>>>(x, wmin, wmax, out);
}